// round 4
// baseline (speedup 1.0000x reference)
#include <cuda_runtime.h>

#define NCLS   20
#define IMGSZ  600.0f
#define BATCH  16
#define NA     65536
#define NM     32
#define TPB    256
#define BLKPI  (NA / TPB)           // 256 blocks per image
#define NBLK   (BATCH * BLKPI)      // 4096 blocks total, 1 anchor per thread
#define L2E    1.4426950408889634f
#define LN2    0.6931471805599453f

// Per-block partials: [0..NBLK)=loc, [NBLK..2N)=cls, [2N..3N)=numpos
__device__ float        g_part[3 * NBLK];
__device__ unsigned int g_count = 0;

__device__ __forceinline__ float ex2f(float x) {
    float y; asm("ex2.approx.ftz.f32 %0, %1;" : "=f"(y) : "f"(x)); return y;
}
__device__ __forceinline__ float lg2f(float x) {
    float y; asm("lg2.approx.ftz.f32 %0, %1;" : "=f"(y) : "f"(x)); return y;
}

// Negative-class focal term in "q*l" units (true term = 0.75*ln2 * q*l):
// q = sigmoid(x)^2, l = log2(1+e^x)
__device__ __forceinline__ float negterm(float x) {
    float t = x * L2E;
    float e = ex2f(t);
    float l = lg2f(1.0f + e);
    float d = t - l;
    float q = ex2f(d + d);
    return q * l;
}

__device__ __forceinline__ float smooth_l1(float d) {
    float ad = fabsf(d);
    return (ad < 1.0f) ? 0.5f * d * d : ad - 0.5f;
}

__global__ void __launch_bounds__(TPB) k_main(
    const float* __restrict__ loc_preds,   // [B, A, 4]
    const float* __restrict__ cls_preds,   // [B, A, 20]
    const float* __restrict__ iou_boxes,   // [A, 4] xywh
    const float* __restrict__ targets,     // [B*M, 6]
    float* __restrict__ out)
{
    __shared__ float4 s_box[NM];    // x1, y1, x2+1, y2+1
    __shared__ float4 s_xywh[NM];   // cx, cy, w, h
    __shared__ float  s_ar[NM];     // (w+1)*(h+1)
    __shared__ int    s_lab[NM];
    __shared__ float  s_red[24];
    __shared__ int    s_last;

    const int tid  = threadIdx.x;
    const int lane = tid & 31;
    const int b    = blockIdx.x >> 8;                  // image index (256 blocks/image)
    const int a    = ((blockIdx.x & 255) << 8) + tid;  // this thread's anchor
    const size_t idx = (size_t)b * NA + (size_t)a;

    // Stage this image's 32 targets
    if (tid < NM) {
        const float* tr = targets + ((b << 5) + tid) * 6;
        float cx = tr[2] * IMGSZ, cy = tr[3] * IMGSZ;
        float w  = tr[4] * IMGSZ, h  = tr[5] * IMGSZ;
        s_xywh[tid] = make_float4(cx, cy, w, h);
        s_box[tid]  = make_float4(cx - 0.5f * w, cy - 0.5f * h,
                                  cx + 0.5f * w + 1.0f, cy + 0.5f * h + 1.0f);
        s_ar[tid]  = (w + 1.0f) * (h + 1.0f);
        s_lab[tid] = (int)tr[1];
    }

    // ---- Dense negative-focal sum, warp-coalesced (lane-agnostic) ----
    // Warp's 32 consecutive anchors own 640 consecutive floats of cls_preds.
    float Aacc = 0.0f;   // sum of q*l over this lane's 20 elems (scaled at end)
    {
        const size_t warp_a0 = idx & ~(size_t)31;  // first anchor idx of this warp
        const float4* wp = (const float4*)(cls_preds + warp_a0 * NCLS);
#pragma unroll
        for (int j = 0; j < 5; j++) {
            float4 q = wp[lane + 32 * j];
            Aacc += negterm(q.x);
            Aacc += negterm(q.y);
            Aacc += negterm(q.z);
            Aacc += negterm(q.w);
        }
    }

    __syncthreads();

    // ---- IoU argmax over 32 targets (division-free) ----
    float4 av = ((const float4*)iou_boxes)[a];
    const float acx = av.x, acy = av.y, aw = av.z, ah = av.w;
    const float ax1 = acx - 0.5f * aw, ay1 = acy - 0.5f * ah;
    const float ax2 = acx + 0.5f * aw + 1.0f, ay2 = acy + 0.5f * ah + 1.0f;
    const float aar = (aw + 1.0f) * (ah + 1.0f);

    float bi = 0.0f, bu = 1.0f;
    int   bm = 0;
#pragma unroll
    for (int m = 0; m < NM; m++) {
        float4 tb = s_box[m];
        float tar = s_ar[m];
        float wi = fminf(ax2, tb.z) - fmaxf(ax1, tb.x);
        float hi = fminf(ay2, tb.w) - fmaxf(ay1, tb.y);
        float inter = fmaxf(wi, 0.0f) * fmaxf(hi, 0.0f);
        float u = (aar + tar) - inter;
        if (inter * bu > bi * u) { bi = inter; bu = u; bm = m; }
    }

    // Thresholds without division: iou = bi/bu, bu > 0
    bool pos = (bi + bi) >= bu;                        // iou >= 0.5
    bool ign = (!pos) && (5.0f * bi > 2.0f * bu);      // 0.4 < iou < 0.5

    float Cacc = 0.0f, Lacc = 0.0f, posf = 0.0f;

    if (ign) {
        // Remove this anchor's 20 negative terms from the warp-dense sum.
        const float4* cp = (const float4*)(cls_preds + idx * NCLS);
        float s = 0.0f;
#pragma unroll
        for (int j = 0; j < 5; j++) {
            float4 q = cp[j];
            s += negterm(q.x) + negterm(q.y) + negterm(q.z) + negterm(q.w);
        }
        Aacc -= s;
    }

    if (pos) {
        posf = 1.0f;
        int m = bm;
        int pc = s_lab[m];
        // cls correction: replace neg term of class pc with the positive-class term
        float x = cls_preds[idx * NCLS + pc];
        float t = x * L2E;
        float e = ex2f(t);
        float l = lg2f(1.0f + e);
        float d = t - l;
        float q = ex2f(d + d);          // sigmoid^2
        float p = ex2f(d);              // sigmoid
        float sp = LN2 * l;             // softplus(x)
        float omp = 1.0f - p;
        Cacc = 0.25f * omp * omp * (sp - x) - (0.75f * LN2) * (q * l);

        // loc loss (SmoothL1, beta=1)
        float4 tw = s_xywh[m];
        float4 lp = ((const float4*)loc_preds)[idx];
        float invw = __fdividef(1.0f, aw);
        float invh = __fdividef(1.0f, ah);
        float tx = (tw.x - acx) * invw;
        float ty = (tw.y - acy) * invh;
        float tww = __logf(tw.z * invw);
        float thh = __logf(tw.w * invh);
        Lacc = smooth_l1(lp.x - tx) + smooth_l1(lp.y - ty)
             + smooth_l1(lp.z - tww) + smooth_l1(lp.w - thh);
    }

    float cls_acc = fmaf(Aacc, 0.75f * LN2, Cacc);

    // ---- Block reduction ----
#pragma unroll
    for (int o = 16; o; o >>= 1) {
        Lacc    += __shfl_down_sync(0xffffffffu, Lacc, o);
        cls_acc += __shfl_down_sync(0xffffffffu, cls_acc, o);
        posf    += __shfl_down_sync(0xffffffffu, posf, o);
    }
    int wid = tid >> 5;
    if (lane == 0) {
        s_red[wid]      = Lacc;
        s_red[8 + wid]  = cls_acc;
        s_red[16 + wid] = posf;
    }
    __syncthreads();
    if (tid == 0) {
        float a0 = 0.f, a1 = 0.f, a2 = 0.f;
#pragma unroll
        for (int i = 0; i < 8; i++) { a0 += s_red[i]; a1 += s_red[8+i]; a2 += s_red[16+i]; }
        g_part[blockIdx.x]            = a0;
        g_part[NBLK + blockIdx.x]     = a1;
        g_part[2 * NBLK + blockIdx.x] = a2;
        __threadfence();
        unsigned int o = atomicAdd(&g_count, 1u);
        s_last = (o == (unsigned)(gridDim.x - 1));
    }
    __syncthreads();

    // ---- Last block finalizes ----
    if (s_last) {
        __threadfence();
        double l = 0.0, c = 0.0, p = 0.0;
        for (int i = tid; i < NBLK; i += TPB) {
            l += (double)g_part[i];
            c += (double)g_part[NBLK + i];
            p += (double)g_part[2 * NBLK + i];
        }
        __shared__ double d_red[3 * 8];
#pragma unroll
        for (int o = 16; o; o >>= 1) {
            l += __shfl_down_sync(0xffffffffu, l, o);
            c += __shfl_down_sync(0xffffffffu, c, o);
            p += __shfl_down_sync(0xffffffffu, p, o);
        }
        if (lane == 0) { d_red[wid] = l; d_red[8 + wid] = c; d_red[16 + wid] = p; }
        __syncthreads();
        if (tid == 0) {
            double L = 0.0, C = 0.0, P = 0.0;
#pragma unroll
            for (int i = 0; i < 8; i++) { L += d_red[i]; C += d_red[8+i]; P += d_red[16+i]; }
            if (P < 1.0) P = 1.0;
            out[0] = (float)((L + C) / P);
            out[1] = (float)(L / P);
            out[2] = (float)(C / P);
            g_count = 0;   // reset for next graph replay
        }
    }
}

extern "C" void kernel_launch(void* const* d_in, const int* in_sizes, int n_in,
                              void* d_out, int out_size) {
    const float* loc_preds = (const float*)d_in[0];
    const float* cls_preds = (const float*)d_in[1];
    const float* iou_boxes = (const float*)d_in[2];
    const float* targets   = (const float*)d_in[3];
    float* out = (float*)d_out;

    k_main<<<NBLK, TPB>>>(loc_preds, cls_preds, iou_boxes, targets, out);
}

// round 6
// speedup vs baseline: 1.0274x; 1.0274x over previous
#include <cuda_runtime.h>

#define NCLS   20
#define IMGSZ  600.0f
#define BATCH  16
#define NA     65536
#define NM     32
#define TPB    256
#define BLKPI  (NA / TPB)           // 256 blocks per image
#define NBLK   (BATCH * BLKPI)      // 4096 blocks, 1 anchor per thread
#define L2E    1.4426950408889634f
#define LN2    0.6931471805599453f

__device__ float        g_part[3 * NBLK];
__device__ unsigned int g_count = 0;

__device__ __forceinline__ float ex2f(float x) {
    float y; asm("ex2.approx.ftz.f32 %0, %1;" : "=f"(y) : "f"(x)); return y;
}
__device__ __forceinline__ float lg2f(float x) {
    float y; asm("lg2.approx.ftz.f32 %0, %1;" : "=f"(y) : "f"(x)); return y;
}

// acc += sigmoid(x)^2 * log2(1+e^x)   (true focal neg term = 0.75*ln2 * this)
__device__ __forceinline__ void negterm_add(float x, float& acc) {
    float t = x * L2E;
    float e = ex2f(t);
    float l = lg2f(1.0f + e);
    float d = t - l;
    float q = ex2f(d + d);
    acc = fmaf(q, l, acc);
}

__device__ __forceinline__ float smooth_l1(float d) {
    float ad = fabsf(d);
    return (ad < 1.0f) ? 0.5f * d * d : ad - 0.5f;
}

__global__ void __launch_bounds__(TPB) k_main(
    const float* __restrict__ loc_preds,   // [B, A, 4]
    const float* __restrict__ cls_preds,   // [B, A, 20]
    const float* __restrict__ iou_boxes,   // [A, 4] xywh
    const float* __restrict__ targets,     // [B*M, 6]
    float* __restrict__ out)
{
    __shared__ float4 s_box[NM];    // (-x1, -y1, x2+1, y2+1)
    __shared__ float4 s_xywh[NM];   // cx, cy, w, h
    __shared__ float  s_ar[NM];     // (w+1)*(h+1), float4-readable
    __shared__ int    s_lab[NM];
    __shared__ float  s_red[24];
    __shared__ int    s_last;

    const int tid  = threadIdx.x;
    const int lane = tid & 31;
    const int b    = blockIdx.x >> 8;                  // 256 blocks per image
    const int a    = ((blockIdx.x & 255) << 8) + tid;
    const size_t idx = (size_t)b * NA + (size_t)a;
    const size_t warp_a0 = idx & ~(size_t)31;          // first anchor of this warp

    if (tid < NM) {
        const float* tr = targets + ((b << 5) + tid) * 6;
        float cx = tr[2] * IMGSZ, cy = tr[3] * IMGSZ;
        float w  = tr[4] * IMGSZ, h  = tr[5] * IMGSZ;
        s_xywh[tid] = make_float4(cx, cy, w, h);
        s_box[tid]  = make_float4(0.5f * w - cx, 0.5f * h - cy,     // -x1, -y1
                                  cx + 0.5f * w + 1.0f, cy + 0.5f * h + 1.0f);
        s_ar[tid]  = (w + 1.0f) * (h + 1.0f);
        s_lab[tid] = (int)tr[1];
    }

    // ---- Dense negative-focal sum, warp-coalesced (lane-agnostic) ----
    float Aacc = 0.0f;
    {
        const float4* wp = (const float4*)(cls_preds + warp_a0 * NCLS);
#pragma unroll
        for (int j = 0; j < 5; j++) {
            float4 q = wp[lane + 32 * j];
            negterm_add(q.x, Aacc);
            negterm_add(q.y, Aacc);
            negterm_add(q.z, Aacc);
            negterm_add(q.w, Aacc);
        }
    }

    __syncthreads();

    // ---- IoU argmax over 32 targets (division-free, min-only bounds) ----
    float4 av = ((const float4*)iou_boxes)[a];
    const float acx = av.x, acy = av.y, aw = av.z, ah = av.w;
    const float nax1 = 0.5f * aw - acx, nay1 = 0.5f * ah - acy;  // -x1, -y1
    const float ax2 = acx + 0.5f * aw + 1.0f, ay2 = acy + 0.5f * ah + 1.0f;
    const float aar = (aw + 1.0f) * (ah + 1.0f);

    float bi = 0.0f, bu = 1.0f;
    int   bm = 0;
#pragma unroll
    for (int mg = 0; mg < NM / 4; mg++) {
        float4 ar4 = ((const float4*)s_ar)[mg];
        float ars[4] = {ar4.x, ar4.y, ar4.z, ar4.w};
#pragma unroll
        for (int mi = 0; mi < 4; mi++) {
            int m = mg * 4 + mi;
            float4 tb = s_box[m];
            // wi = min(ax2,tx2) - max(ax1,tx1) = min(ax2,tx2) + min(-ax1,-tx1)
            float wi = fminf(ax2, tb.z) + fminf(nax1, tb.x);
            float hi = fminf(ay2, tb.w) + fminf(nay1, tb.y);
            float inter = fmaxf(wi, 0.0f) * fmaxf(hi, 0.0f);
            float u = (aar + ars[mi]) - inter;
            if (inter * bu > bi * u) { bi = inter; bu = u; bm = m; }
        }
    }

    bool pos = (bi + bi) >= bu;                     // iou >= 0.5
    bool ign = (!pos) && (5.0f * bi > 2.0f * bu);   // 0.4 < iou < 0.5

    // ---- Warp-cooperative ignored-anchor corrections (lanes 0..19 active) ----
    float Corr = 0.0f;   // terms to SUBTRACT from the dense sum
    unsigned ignm = __ballot_sync(0xffffffffu, ign);
    while (ignm) {
        int src = __ffs(ignm) - 1;
        ignm &= ignm - 1;
        const float* cp = cls_preds + (warp_a0 + (size_t)src) * NCLS;
        if (lane < NCLS) negterm_add(cp[lane], Corr);
    }

    // ---- Positive anchors: cls fix + loc loss (rare, per-lane) ----
    float Cacc = 0.0f, Lacc = 0.0f, posf = 0.0f;
    if (pos) {
        posf = 1.0f;
        int m = bm;
        int pc = s_lab[m];
        float x = cls_preds[idx * NCLS + pc];
        float t = x * L2E;
        float e = ex2f(t);
        float l = lg2f(1.0f + e);
        float d = t - l;
        float q = ex2f(d + d);          // sigmoid^2
        float p = ex2f(d);              // sigmoid
        float sp = LN2 * l;             // softplus(x)
        float omp = 1.0f - p;
        Cacc = 0.25f * omp * omp * (sp - x) - (0.75f * LN2) * (q * l);

        float4 tw = s_xywh[m];
        float4 lp = ((const float4*)loc_preds)[idx];
        float invw = __fdividef(1.0f, aw);
        float invh = __fdividef(1.0f, ah);
        float tx = (tw.x - acx) * invw;
        float ty = (tw.y - acy) * invh;
        float tww = __logf(tw.z * invw);
        float thh = __logf(tw.w * invh);
        Lacc = smooth_l1(lp.x - tx) + smooth_l1(lp.y - ty)
             + smooth_l1(lp.z - tww) + smooth_l1(lp.w - thh);
    }

    float cls_acc = fmaf(Aacc - Corr, 0.75f * LN2, Cacc);

    // ---- Block reduction ----
#pragma unroll
    for (int o = 16; o; o >>= 1) {
        Lacc    += __shfl_down_sync(0xffffffffu, Lacc, o);
        cls_acc += __shfl_down_sync(0xffffffffu, cls_acc, o);
        posf    += __shfl_down_sync(0xffffffffu, posf, o);
    }
    int wid = tid >> 5;
    if (lane == 0) {
        s_red[wid]      = Lacc;
        s_red[8 + wid]  = cls_acc;
        s_red[16 + wid] = posf;
    }
    __syncthreads();
    if (tid == 0) {
        float a0 = 0.f, a1 = 0.f, a2 = 0.f;
#pragma unroll
        for (int i = 0; i < 8; i++) { a0 += s_red[i]; a1 += s_red[8+i]; a2 += s_red[16+i]; }
        g_part[blockIdx.x]            = a0;
        g_part[NBLK + blockIdx.x]     = a1;
        g_part[2 * NBLK + blockIdx.x] = a2;
        __threadfence();
        unsigned int o = atomicAdd(&g_count, 1u);
        s_last = (o == (unsigned)(gridDim.x - 1));
    }
    __syncthreads();

    // ---- Last block finalizes ----
    if (s_last) {
        __threadfence();
        double l = 0.0, c = 0.0, p = 0.0;
        for (int i = tid; i < NBLK; i += TPB) {
            l += (double)g_part[i];
            c += (double)g_part[NBLK + i];
            p += (double)g_part[2 * NBLK + i];
        }
        __shared__ double d_red[3 * 8];
#pragma unroll
        for (int o = 16; o; o >>= 1) {
            l += __shfl_down_sync(0xffffffffu, l, o);
            c += __shfl_down_sync(0xffffffffu, c, o);
            p += __shfl_down_sync(0xffffffffu, p, o);
        }
        if (lane == 0) { d_red[wid] = l; d_red[8 + wid] = c; d_red[16 + wid] = p; }
        __syncthreads();
        if (tid == 0) {
            double L = 0.0, C = 0.0, P = 0.0;
#pragma unroll
            for (int i = 0; i < 8; i++) { L += d_red[i]; C += d_red[8+i]; P += d_red[16+i]; }
            if (P < 1.0) P = 1.0;
            out[0] = (float)((L + C) / P);
            out[1] = (float)(L / P);
            out[2] = (float)(C / P);
            g_count = 0;   // reset for next graph replay
        }
    }
}

extern "C" void kernel_launch(void* const* d_in, const int* in_sizes, int n_in,
                              void* d_out, int out_size) {
    const float* loc_preds = (const float*)d_in[0];
    const float* cls_preds = (const float*)d_in[1];
    const float* iou_boxes = (const float*)d_in[2];
    const float* targets   = (const float*)d_in[3];
    float* out = (float*)d_out;

    k_main<<<NBLK, TPB>>>(loc_preds, cls_preds, iou_boxes, targets, out);
}

// round 10
// speedup vs baseline: 1.0775x; 1.0487x over previous
#include <cuda_runtime.h>

#define NCLS   20
#define IMGSZ  600.0f
#define BATCH  16
#define NA     65536
#define NM     32
#define TPB    256
#define APB    512                  // anchors per block (2 per thread)
#define BLKPI  (NA / APB)           // 128 blocks per image
#define NBLK   (BATCH * BLKPI)      // 2048 blocks
#define L2E    1.4426950408889634f
#define LN2    0.6931471805599453f

__device__ float        g_part[3 * NBLK];
__device__ unsigned int g_count = 0;

__device__ __forceinline__ float ex2f(float x) {
    float y; asm("ex2.approx.ftz.f32 %0, %1;" : "=f"(y) : "f"(x)); return y;
}
__device__ __forceinline__ float lg2f(float x) {
    float y; asm("lg2.approx.ftz.f32 %0, %1;" : "=f"(y) : "f"(x)); return y;
}

// acc += sigmoid(x)^2 * log2(1+e^x)   (true focal neg term = 0.75*ln2 * this)
__device__ __forceinline__ void negterm_add(float x, float& acc) {
    float t = x * L2E;
    float e = ex2f(t);
    float l = lg2f(1.0f + e);
    float d = t - l;
    float q = ex2f(d + d);
    acc = fmaf(q, l, acc);
}

__device__ __forceinline__ float smooth_l1(float d) {
    float ad = fabsf(d);
    return (ad < 1.0f) ? 0.5f * d * d : ad - 0.5f;
}

__global__ void __launch_bounds__(TPB) k_main(
    const float* __restrict__ loc_preds,   // [B, A, 4]
    const float* __restrict__ cls_preds,   // [B, A, 20]
    const float* __restrict__ iou_boxes,   // [A, 4] xywh
    const float* __restrict__ targets,     // [B*M, 6]
    float* __restrict__ out)
{
    __shared__ float4 s_box[NM];    // (-x1, -y1, x2+1, y2+1)
    __shared__ float4 s_xywh[NM];   // cx, cy, w, h
    __shared__ float  s_ar[NM];     // (w+1)*(h+1)
    __shared__ int    s_lab[NM];
    __shared__ float  s_red[24];
    __shared__ int    s_last;

    const int tid  = threadIdx.x;
    const int lane = tid & 31;
    const int b    = blockIdx.x >> 7;                  // 128 blocks per image
    const int a0   = ((blockIdx.x & 127) << 9) + tid;  // anchor A
    const int a1   = a0 + 256;                         // anchor B
    const size_t idx0 = (size_t)b * NA + (size_t)a0;
    const size_t idx1 = idx0 + 256;
    const size_t warp_a0 = idx0 & ~(size_t)31;         // warp's first anchor (set A)

    if (tid < NM) {
        const float* tr = targets + ((b << 5) + tid) * 6;
        float cx = tr[2] * IMGSZ, cy = tr[3] * IMGSZ;
        float w  = tr[4] * IMGSZ, h  = tr[5] * IMGSZ;
        s_xywh[tid] = make_float4(cx, cy, w, h);
        s_box[tid]  = make_float4(0.5f * w - cx, 0.5f * h - cy,     // -x1, -y1
                                  cx + 0.5f * w + 1.0f, cy + 0.5f * h + 1.0f);
        s_ar[tid]  = (w + 1.0f) * (h + 1.0f);
        s_lab[tid] = (int)tr[1];
    }

    // ---- Dense negative-focal sum for BOTH 32-anchor spans of this warp ----
    float Aacc = 0.0f;
    {
        const float4* wpA = (const float4*)(cls_preds + warp_a0 * NCLS);
        const float4* wpB = (const float4*)(cls_preds + (warp_a0 + 256) * NCLS);
#pragma unroll
        for (int j = 0; j < 5; j++) {
            float4 qa = wpA[lane + 32 * j];
            float4 qb = wpB[lane + 32 * j];
            negterm_add(qa.x, Aacc); negterm_add(qa.y, Aacc);
            negterm_add(qa.z, Aacc); negterm_add(qa.w, Aacc);
            negterm_add(qb.x, Aacc); negterm_add(qb.y, Aacc);
            negterm_add(qb.z, Aacc); negterm_add(qb.w, Aacc);
        }
    }

    __syncthreads();

    // ---- IoU argmax, two anchors, shared target reads ----
    float4 av0 = ((const float4*)iou_boxes)[a0];
    float4 av1 = ((const float4*)iou_boxes)[a1];
    const float nax1A = 0.5f * av0.z - av0.x, nay1A = 0.5f * av0.w - av0.y;
    const float ax2A  = av0.x + 0.5f * av0.z + 1.0f, ay2A = av0.y + 0.5f * av0.w + 1.0f;
    const float aarA  = (av0.z + 1.0f) * (av0.w + 1.0f);
    const float nax1B = 0.5f * av1.z - av1.x, nay1B = 0.5f * av1.w - av1.y;
    const float ax2B  = av1.x + 0.5f * av1.z + 1.0f, ay2B = av1.y + 0.5f * av1.w + 1.0f;
    const float aarB  = (av1.z + 1.0f) * (av1.w + 1.0f);

    // State: best inter (bi), best S = aar+tar (bS).  iou = bi/(bS-bi).
    // new beats best  <=>  inter_new*bS_best > bi_best*S_new   (cross terms cancel)
    float biA = 0.0f, bSA = 1.0f; int bmA = 0;
    float biB = 0.0f, bSB = 1.0f; int bmB = 0;
#pragma unroll
    for (int mg = 0; mg < NM / 4; mg++) {
        float4 ar4 = ((const float4*)s_ar)[mg];
        float ars[4] = {ar4.x, ar4.y, ar4.z, ar4.w};
#pragma unroll
        for (int mi = 0; mi < 4; mi++) {
            int m = mg * 4 + mi;
            float4 tb = s_box[m];
            float wiA = fminf(ax2A, tb.z) + fminf(nax1A, tb.x);
            float hiA = fminf(ay2A, tb.w) + fminf(nay1A, tb.y);
            float inA = fmaxf(wiA, 0.0f) * fmaxf(hiA, 0.0f);
            float SA  = aarA + ars[mi];
            if (inA * bSA > biA * SA) { biA = inA; bSA = SA; bmA = m; }

            float wiB = fminf(ax2B, tb.z) + fminf(nax1B, tb.x);
            float hiB = fminf(ay2B, tb.w) + fminf(nay1B, tb.y);
            float inB = fmaxf(wiB, 0.0f) * fmaxf(hiB, 0.0f);
            float SB  = aarB + ars[mi];
            if (inB * bSB > biB * SB) { biB = inB; bSB = SB; bmB = m; }
        }
    }

    // iou >= 0.5  <=>  3*bi >= bS ;  iou > 0.4  <=>  7*bi > 2*bS
    bool posA = 3.0f * biA >= bSA;
    bool ignA = (!posA) && (7.0f * biA > 2.0f * bSA);
    bool posB = 3.0f * biB >= bSB;
    bool ignB = (!posB) && (7.0f * biB > 2.0f * bSB);

    // ---- Warp-cooperative ignored-anchor corrections (two 32-bit masks) ----
    float Corr = 0.0f;
    unsigned mA = __ballot_sync(0xffffffffu, ignA);
    unsigned mB = __ballot_sync(0xffffffffu, ignB);
    while (mA) {
        int src = __ffs(mA) - 1;
        mA &= mA - 1;
        const float* cp = cls_preds + (warp_a0 + (size_t)src) * NCLS;
        if (lane < NCLS) negterm_add(cp[lane], Corr);
    }
    while (mB) {
        int src = __ffs(mB) - 1;
        mB &= mB - 1;
        const float* cp = cls_preds + (warp_a0 + 256 + (size_t)src) * NCLS;
        if (lane < NCLS) negterm_add(cp[lane], Corr);
    }

    // ---- Positive anchors (rare) ----
    float Cacc = 0.0f, Lacc = 0.0f, posf = 0.0f;
#pragma unroll
    for (int s = 0; s < 2; s++) {
        bool pos = s ? posB : posA;
        if (!pos) continue;
        int m = s ? bmB : bmA;
        size_t idx = s ? idx1 : idx0;
        float acx = s ? av1.x : av0.x, acy = s ? av1.y : av0.y;
        float aw  = s ? av1.z : av0.z, ah  = s ? av1.w : av0.w;

        posf += 1.0f;
        int pc = s_lab[m];
        float x = cls_preds[idx * NCLS + pc];
        float t = x * L2E;
        float e = ex2f(t);
        float l = lg2f(1.0f + e);
        float d = t - l;
        float q = ex2f(d + d);          // sigmoid^2
        float p = ex2f(d);              // sigmoid
        float sp = LN2 * l;             // softplus(x)
        float omp = 1.0f - p;
        Cacc += 0.25f * omp * omp * (sp - x) - (0.75f * LN2) * (q * l);

        float4 tw = s_xywh[m];
        float4 lp = ((const float4*)loc_preds)[idx];
        float invw = __fdividef(1.0f, aw);
        float invh = __fdividef(1.0f, ah);
        float tx = (tw.x - acx) * invw;
        float ty = (tw.y - acy) * invh;
        float tww = __logf(tw.z * invw);
        float thh = __logf(tw.w * invh);
        Lacc += smooth_l1(lp.x - tx) + smooth_l1(lp.y - ty)
              + smooth_l1(lp.z - tww) + smooth_l1(lp.w - thh);
    }

    float cls_acc = fmaf(Aacc - Corr, 0.75f * LN2, Cacc);

    // ---- Block reduction ----
#pragma unroll
    for (int o = 16; o; o >>= 1) {
        Lacc    += __shfl_down_sync(0xffffffffu, Lacc, o);
        cls_acc += __shfl_down_sync(0xffffffffu, cls_acc, o);
        posf    += __shfl_down_sync(0xffffffffu, posf, o);
    }
    int wid = tid >> 5;
    if (lane == 0) {
        s_red[wid]      = Lacc;
        s_red[8 + wid]  = cls_acc;
        s_red[16 + wid] = posf;
    }
    __syncthreads();
    if (tid == 0) {
        float r0 = 0.f, r1 = 0.f, r2 = 0.f;
#pragma unroll
        for (int i = 0; i < 8; i++) { r0 += s_red[i]; r1 += s_red[8+i]; r2 += s_red[16+i]; }
        g_part[blockIdx.x]            = r0;
        g_part[NBLK + blockIdx.x]     = r1;
        g_part[2 * NBLK + blockIdx.x] = r2;
        __threadfence();
        unsigned int o = atomicAdd(&g_count, 1u);
        s_last = (o == (unsigned)(gridDim.x - 1));
    }
    __syncthreads();

    // ---- Last block finalizes ----
    if (s_last) {
        __threadfence();
        double l = 0.0, c = 0.0, p = 0.0;
        for (int i = tid; i < NBLK; i += TPB) {
            l += (double)g_part[i];
            c += (double)g_part[NBLK + i];
            p += (double)g_part[2 * NBLK + i];
        }
        __shared__ double d_red[3 * 8];
#pragma unroll
        for (int o = 16; o; o >>= 1) {
            l += __shfl_down_sync(0xffffffffu, l, o);
            c += __shfl_down_sync(0xffffffffu, c, o);
            p += __shfl_down_sync(0xffffffffu, p, o);
        }
        if (lane == 0) { d_red[wid] = l; d_red[8 + wid] = c; d_red[16 + wid] = p; }
        __syncthreads();
        if (tid == 0) {
            double L = 0.0, C = 0.0, P = 0.0;
#pragma unroll
            for (int i = 0; i < 8; i++) { L += d_red[i]; C += d_red[8+i]; P += d_red[16+i]; }
            if (P < 1.0) P = 1.0;
            out[0] = (float)((L + C) / P);
            out[1] = (float)(L / P);
            out[2] = (float)(C / P);
            g_count = 0;   // reset for next graph replay
        }
    }
}

extern "C" void kernel_launch(void* const* d_in, const int* in_sizes, int n_in,
                              void* d_out, int out_size) {
    const float* loc_preds = (const float*)d_in[0];
    const float* cls_preds = (const float*)d_in[1];
    const float* iou_boxes = (const float*)d_in[2];
    const float* targets   = (const float*)d_in[3];
    float* out = (float*)d_out;

    k_main<<<NBLK, TPB>>>(loc_preds, cls_preds, iou_boxes, targets, out);
}